// round 9
// baseline (speedup 1.0000x reference)
#include <cuda_runtime.h>
#include <cstdint>
#include <math.h>

#define NBATCH 16
#define NNODE  1024
#define HD     256
#define NROWS  (NBATCH*NNODE)
#define TOTEL  16777216

__device__ float d_hid[NROWS*768];
__device__ float d_hs [NROWS*HD];
__device__ float d_g  [NROWS*HD];
__device__ float d_u1 [NROWS*HD];
__device__ float d_u2 [NROWS*HD];
__device__ float d_u3 [NROWS*HD];
__device__ float d_u4 [NROWS*HD];
__device__ float d_hp [NROWS*HD];
__device__ float d_mid[NROWS*HD];
__device__ float d_logits[TOTEL];
__device__ float d_dis[NROWS];
__device__ float d_invdeg[NROWS];
__device__ float d_Rv[NROWS];
__device__ float d_Cv[NROWS];
__device__ float d_Tv[NROWS];

__device__ __forceinline__ float leakyf(float x){ return x > 0.f ? x : 0.01f*x; }

__global__ void k_adj_stats(const float* __restrict__ adj){
    int row  = blockIdx.x*8 + (threadIdx.x>>5);
    int lane = threadIdx.x & 31;
    const float* a = adj + (size_t)row*NNODE;
    float s = 0.f;
    #pragma unroll
    for (int k=0;k<32;k++) s += a[lane + 32*k];
    #pragma unroll
    for (int o=16;o;o>>=1) s += __shfl_xor_sync(0xffffffffu, s, o);
    if (lane==0){ d_dis[row] = rsqrtf(s + 1.f); d_invdeg[row] = 1.f/s; }
}

__global__ void k_scale_hs(int off){
    int idx = blockIdx.x*256 + threadIdx.x;
    int row = idx >> 8, col = idx & 255;
    d_hs[idx] = d_dis[row] * d_hid[(size_t)row*768 + off + col];
}

#define BM 128
#define BN 128
#define BK 16

// batched adj GEMM, double-buffered, conflict-free split fragments
// mode1: out=leaky(dis*(acc+aux)); mode2: out=0.5*(aux+acc*invdeg)
__global__ __launch_bounds__(256,2) void k_bgemm(
    const float* __restrict__ Aadj, const float* __restrict__ B, int ldb,
    float* __restrict__ Cc, int ldc, int mode,
    const float* __restrict__ aux, int ldaux, const float* __restrict__ vec)
{
    int bb = blockIdx.z;
    int n0 = blockIdx.x * BN;
    int m0 = blockIdx.y * BM;
    const float* Ab = Aadj + (size_t)bb*NNODE*NNODE;
    __shared__ float As[2][BK][BM];
    __shared__ float Bs[2][BK][BN];
    int tid  = threadIdx.x;
    int arow = tid >> 1;
    int acol = (tid & 1) * 8;
    int brow = tid >> 4;
    int bcol = (tid & 15) * 8;
    int ty = tid >> 4, tx = tid & 15;

    const float* aptr = Ab + (size_t)(m0+arow)*NNODE + acol;
    const float* bptr = B + (size_t)(bb*NNODE + brow)*ldb + n0 + bcol;

    float4 a0 = *(const float4*)(aptr);
    float4 a1 = *(const float4*)(aptr + 4);
    float4 b0 = *(const float4*)(bptr);
    float4 b1 = *(const float4*)(bptr + 4);
    As[0][acol+0][arow]=a0.x; As[0][acol+1][arow]=a0.y; As[0][acol+2][arow]=a0.z; As[0][acol+3][arow]=a0.w;
    As[0][acol+4][arow]=a1.x; As[0][acol+5][arow]=a1.y; As[0][acol+6][arow]=a1.z; As[0][acol+7][arow]=a1.w;
    *(float4*)&Bs[0][brow][bcol]   = b0;
    *(float4*)&Bs[0][brow][bcol+4] = b1;
    __syncthreads();

    float acc[8][8] = {};
    const int ntile = NNODE/BK;
    for (int t = 0; t < ntile; t++){
        int cur = t & 1;
        if (t+1 < ntile){
            a0 = *(const float4*)(aptr + (t+1)*BK);
            a1 = *(const float4*)(aptr + (t+1)*BK + 4);
            b0 = *(const float4*)(bptr + (size_t)(t+1)*BK*ldb);
            b1 = *(const float4*)(bptr + (size_t)(t+1)*BK*ldb + 4);
        }
        #pragma unroll
        for (int k=0;k<BK;k++){
            float4 fa0 = *(const float4*)&As[cur][k][ty*4];
            float4 fa1 = *(const float4*)&As[cur][k][64+ty*4];
            float4 fb0 = *(const float4*)&Bs[cur][k][tx*4];
            float4 fb1 = *(const float4*)&Bs[cur][k][64+tx*4];
            float ar[8] = {fa0.x,fa0.y,fa0.z,fa0.w,fa1.x,fa1.y,fa1.z,fa1.w};
            float br[8] = {fb0.x,fb0.y,fb0.z,fb0.w,fb1.x,fb1.y,fb1.z,fb1.w};
            #pragma unroll
            for (int m=0;m<8;m++)
                #pragma unroll
                for (int n=0;n<8;n++)
                    acc[m][n] = fmaf(ar[m], br[n], acc[m][n]);
        }
        if (t+1 < ntile){
            int nxt = cur ^ 1;
            As[nxt][acol+0][arow]=a0.x; As[nxt][acol+1][arow]=a0.y; As[nxt][acol+2][arow]=a0.z; As[nxt][acol+3][arow]=a0.w;
            As[nxt][acol+4][arow]=a1.x; As[nxt][acol+5][arow]=a1.y; As[nxt][acol+6][arow]=a1.z; As[nxt][acol+7][arow]=a1.w;
            *(float4*)&Bs[nxt][brow][bcol]   = b0;
            *(float4*)&Bs[nxt][brow][bcol+4] = b1;
            __syncthreads();
        }
    }
    #pragma unroll
    for (int mh=0; mh<2; mh++)
    #pragma unroll
    for (int mi=0; mi<4; mi++){
        int m = mh*4+mi;
        size_t gi = (size_t)(bb*NNODE + m0 + mh*64 + ty*4 + mi);
        float dv = vec[gi];
        const float* auxr = aux + gi*(size_t)ldaux + n0;
        float* outr = Cc + gi*(size_t)ldc + n0;
        #pragma unroll
        for (int nh=0; nh<2; nh++){
            int colb = nh*64 + tx*4;
            float4 ax = *(const float4*)(auxr + colb);
            float4 o;
            if (mode == 1){
                o.x = leakyf(dv*(acc[m][nh*4+0]+ax.x));
                o.y = leakyf(dv*(acc[m][nh*4+1]+ax.y));
                o.z = leakyf(dv*(acc[m][nh*4+2]+ax.z));
                o.w = leakyf(dv*(acc[m][nh*4+3]+ax.w));
            } else {
                o.x = 0.5f*(ax.x + acc[m][nh*4+0]*dv);
                o.y = 0.5f*(ax.y + acc[m][nh*4+1]*dv);
                o.z = 0.5f*(ax.z + acc[m][nh*4+2]*dv);
                o.w = 0.5f*(ax.w + acc[m][nh*4+3]*dv);
            }
            *(float4*)(outr + colb) = o;
        }
    }
}

// dense NT GEMM, double-buffered, conflict-free split fragments
__global__ __launch_bounds__(256,2) void k_gemm_nt(
    const float* __restrict__ A, int lda,
    const float* __restrict__ W, int K, const float* __restrict__ bias,
    float* __restrict__ Cc, int ldc, int act)
{
    int n0 = blockIdx.x * BN;
    int m0 = blockIdx.y * BM;
    __shared__ float As[2][BK][BM];
    __shared__ float Bs[2][BK][BN];
    int tid  = threadIdx.x;
    int arow = tid >> 1;
    int acol = (tid & 1) * 8;
    int ty = tid >> 4, tx = tid & 15;

    const float* aptr = A + (size_t)(m0+arow)*lda + acol;
    const float* wptr = W + (size_t)(n0+arow)*K   + acol;

    float4 a0 = *(const float4*)(aptr);
    float4 a1 = *(const float4*)(aptr + 4);
    float4 w0 = *(const float4*)(wptr);
    float4 w1 = *(const float4*)(wptr + 4);
    As[0][acol+0][arow]=a0.x; As[0][acol+1][arow]=a0.y; As[0][acol+2][arow]=a0.z; As[0][acol+3][arow]=a0.w;
    As[0][acol+4][arow]=a1.x; As[0][acol+5][arow]=a1.y; As[0][acol+6][arow]=a1.z; As[0][acol+7][arow]=a1.w;
    Bs[0][acol+0][arow]=w0.x; Bs[0][acol+1][arow]=w0.y; Bs[0][acol+2][arow]=w0.z; Bs[0][acol+3][arow]=w0.w;
    Bs[0][acol+4][arow]=w1.x; Bs[0][acol+5][arow]=w1.y; Bs[0][acol+6][arow]=w1.z; Bs[0][acol+7][arow]=w1.w;
    __syncthreads();

    float acc[8][8] = {};
    const int ntile = K/BK;
    for (int t = 0; t < ntile; t++){
        int cur = t & 1;
        if (t+1 < ntile){
            a0 = *(const float4*)(aptr + (t+1)*BK);
            a1 = *(const float4*)(aptr + (t+1)*BK + 4);
            w0 = *(const float4*)(wptr + (t+1)*BK);
            w1 = *(const float4*)(wptr + (t+1)*BK + 4);
        }
        #pragma unroll
        for (int k=0;k<BK;k++){
            float4 fa0 = *(const float4*)&As[cur][k][ty*4];
            float4 fa1 = *(const float4*)&As[cur][k][64+ty*4];
            float4 fb0 = *(const float4*)&Bs[cur][k][tx*4];
            float4 fb1 = *(const float4*)&Bs[cur][k][64+tx*4];
            float ar[8] = {fa0.x,fa0.y,fa0.z,fa0.w,fa1.x,fa1.y,fa1.z,fa1.w};
            float br[8] = {fb0.x,fb0.y,fb0.z,fb0.w,fb1.x,fb1.y,fb1.z,fb1.w};
            #pragma unroll
            for (int m=0;m<8;m++)
                #pragma unroll
                for (int n=0;n<8;n++)
                    acc[m][n] = fmaf(ar[m], br[n], acc[m][n]);
        }
        if (t+1 < ntile){
            int nxt = cur ^ 1;
            As[nxt][acol+0][arow]=a0.x; As[nxt][acol+1][arow]=a0.y; As[nxt][acol+2][arow]=a0.z; As[nxt][acol+3][arow]=a0.w;
            As[nxt][acol+4][arow]=a1.x; As[nxt][acol+5][arow]=a1.y; As[nxt][acol+6][arow]=a1.z; As[nxt][acol+7][arow]=a1.w;
            Bs[nxt][acol+0][arow]=w0.x; Bs[nxt][acol+1][arow]=w0.y; Bs[nxt][acol+2][arow]=w0.z; Bs[nxt][acol+3][arow]=w0.w;
            Bs[nxt][acol+4][arow]=w1.x; Bs[nxt][acol+5][arow]=w1.y; Bs[nxt][acol+6][arow]=w1.z; Bs[nxt][acol+7][arow]=w1.w;
            __syncthreads();
        }
    }
    #pragma unroll
    for (int mh=0; mh<2; mh++)
    #pragma unroll
    for (int mi=0; mi<4; mi++){
        int m = mh*4+mi;
        size_t gi = (size_t)(m0 + mh*64 + ty*4 + mi);
        float* outr = Cc + gi*(size_t)ldc + n0;
        #pragma unroll
        for (int nh=0; nh<2; nh++){
            int colb = nh*64 + tx*4;
            float4 bs = *(const float4*)(bias + n0 + colb);
            float4 o;
            o.x = acc[m][nh*4+0] + bs.x;
            o.y = acc[m][nh*4+1] + bs.y;
            o.z = acc[m][nh*4+2] + bs.z;
            o.w = acc[m][nh*4+3] + bs.w;
            if (act == 1){
                o.x=leakyf(o.x); o.y=leakyf(o.y); o.z=leakyf(o.z); o.w=leakyf(o.w);
            } else if (act == 2){
                o.x=tanhf(o.x)*40.f; o.y=tanhf(o.y)*40.f; o.z=tanhf(o.z)*40.f; o.w=tanhf(o.w)*40.f;
            }
            *(float4*)(outr + colb) = o;
        }
    }
}

// channel attention + weighted mean over 4 channels
__global__ void k_attn(int off, const float* __restrict__ avec){
    int i = blockIdx.x, d = threadIdx.x;
    size_t b = (size_t)i*HD + d;
    float x  = d_hid[(size_t)i*768 + off + d];
    float c0 = d_g[b];
    float u1 = d_u1[b], u2 = d_u2[b], u4 = d_u4[b];
    float c1 = fabsf(x - u1), c2 = fabsf(u1 - u2), c3 = fabsf(u2 - u4);
    float ah = avec[256 + d];
    float e0 = fmaxf(c0, 0.f)*ah, e1 = c1*ah, e2 = c2*ah, e3 = c3*ah;
    #pragma unroll
    for (int o=16;o;o>>=1){
        e0 += __shfl_xor_sync(0xffffffffu, e0, o);
        e1 += __shfl_xor_sync(0xffffffffu, e1, o);
        e2 += __shfl_xor_sync(0xffffffffu, e2, o);
        e3 += __shfl_xor_sync(0xffffffffu, e3, o);
    }
    __shared__ float sred[4][8];
    __shared__ float tot[4];
    int w = d >> 5;
    if ((d & 31) == 0){ sred[0][w]=e0; sred[1][w]=e1; sred[2][w]=e2; sred[3][w]=e3; }
    __syncthreads();
    if (d < 4){
        float t = 0.f;
        #pragma unroll
        for (int ww=0; ww<8; ww++) t += sred[d][ww];
        tot[d] = t;
    }
    __syncthreads();
    float E0=tot[0], E1=tot[1], E2=tot[2], E3=tot[3];
    float m = fmaxf(fmaxf(E0,E1), fmaxf(E2,E3));
    float w0=__expf(E0-m), w1=__expf(E1-m), w2=__expf(E2-m), w3=__expf(E3-m);
    float inv = 0.25f / (w0+w1+w2+w3);
    d_hp[b] = inv * (w0*c0 + w1*c1 + w2*c2 + w3*c3);
}

// Threefry-2x32-20, key (0,42)
__device__ __forceinline__ void threefry(unsigned x0, unsigned x1, unsigned& o0, unsigned& o1){
    const unsigned ks0 = 0u, ks1 = 42u, ks2 = 0x1BD11BDAu ^ 42u;
    x0 += ks0; x1 += ks1;
#define TFR(r) { x0 += x1; x1 = (x1<<(r))|(x1>>(32-(r))); x1 ^= x0; }
    TFR(13) TFR(15) TFR(26) TFR(6)   x0+=ks1; x1+=ks2+1u;
    TFR(17) TFR(29) TFR(16) TFR(24)  x0+=ks2; x1+=ks0+2u;
    TFR(13) TFR(15) TFR(26) TFR(6)   x0+=ks0; x1+=ks1+3u;
    TFR(17) TFR(29) TFR(16) TFR(24)  x0+=ks1; x1+=ks2+4u;
    TFR(13) TFR(15) TFR(26) TFR(6)   x0+=ks2; x1+=ks0+5u;
#undef TFR
    o0 = x0; o1 = x1;
}

__device__ __forceinline__ float gumb(unsigned bits){
    float u = __uint_as_float((bits >> 9) | 0x3F800000u) - 1.0f;
    return -logf(-logf(u + 1e-20f) + 1e-20f) * 0.05f;
}

// JAX partitionable threefry: counter = uint64 t -> (hi=0, lo=t), out = o0^o1
__global__ void k_z0(float* __restrict__ z0){
    unsigned t = blockIdx.x*256u + threadIdx.x;
    unsigned o0, o1;
    threefry(0u, t, o0, o1);
    z0[t] = (d_logits[t] + gumb(o0 ^ o1)) * 10.0f;
}

__global__ void k_zeroC(){ d_Cv[blockIdx.x*256 + threadIdx.x] = 0.f; }

// R[row] = lse_j(Z[row,:] - C[b,:]); one warp per row
__global__ void k_row_lse(const float* __restrict__ Z){
    int row  = blockIdx.x*8 + (threadIdx.x>>5);
    int lane = threadIdx.x & 31;
    int b    = row >> 10;
    const float* z = Z + (size_t)row*NNODE;
    const float* c = d_Cv + b*NNODE;
    float v[32];
    float m = -3.4e38f;
    #pragma unroll
    for (int k=0;k<32;k++){ v[k] = z[lane + 32*k] - c[lane + 32*k]; m = fmaxf(m, v[k]); }
    #pragma unroll
    for (int o=16;o;o>>=1) m = fmaxf(m, __shfl_xor_sync(0xffffffffu, m, o));
    float s = 0.f;
    #pragma unroll
    for (int k=0;k<32;k++) s += __expf(v[k] - m);
    #pragma unroll
    for (int o=16;o;o>>=1) s += __shfl_xor_sync(0xffffffffu, s, o);
    if (lane==0) d_Rv[row] = m + __logf(s);
}

__device__ __forceinline__ void online_lse(float v, float& m, float& s){
    if (v > m){ s = s*__expf(m - v) + 1.f; m = v; }
    else      { s += __expf(v - m); }
}
__device__ __forceinline__ void merge_lse(float& M, float& S, float mg, float sg){
    if (mg > M){ S = S*__expf(M - mg) + sg; M = mg; }
    else       { S += sg*__expf(mg - M); }
}

// C[b,j] = lse_i(Z[b,i,j] - R[b,i]); vectorized: thread owns 4 consecutive cols
// grid = 16 batches x 8 chunks(128 cols); block 256 = 32 colgroups x 8 rowgroups(128 rows)
__global__ void k_col_lse(const float* __restrict__ Z){
    int b     = blockIdx.x >> 3;
    int chunk = blockIdx.x & 7;
    int cg    = threadIdx.x & 31;
    int rg    = threadIdx.x >> 5;
    __shared__ float rs[NNODE];
    for (int k=threadIdx.x; k<NNODE; k+=256) rs[k] = d_Rv[b*NNODE + k];
    __syncthreads();
    const float4* z = (const float4*)(Z + (size_t)b*NNODE*NNODE) + chunk*32 + cg;
    float4 m = {-3.4e38f,-3.4e38f,-3.4e38f,-3.4e38f};
    float4 s = {0.f,0.f,0.f,0.f};
    int i0 = rg*128;
    for (int i=i0; i<i0+128; i++){
        float4 v = z[(size_t)i*256];
        float r = rs[i];
        online_lse(v.x - r, m.x, s.x);
        online_lse(v.y - r, m.y, s.y);
        online_lse(v.z - r, m.z, s.z);
        online_lse(v.w - r, m.w, s.w);
    }
    __shared__ float4 sm8[8][32], ss8[8][32];
    sm8[rg][cg] = m; ss8[rg][cg] = s;
    __syncthreads();
    if (rg == 0){
        float4 M = m, S = s;
        #pragma unroll
        for (int g=1; g<8; g++){
            float4 mg = sm8[g][cg], sg = ss8[g][cg];
            merge_lse(M.x, S.x, mg.x, sg.x);
            merge_lse(M.y, S.y, mg.y, sg.y);
            merge_lse(M.z, S.z, mg.z, sg.z);
            merge_lse(M.w, S.w, mg.w, sg.w);
        }
        int j = b*NNODE + chunk*128 + cg*4;
        d_Cv[j+0] = M.x + __logf(S.x);
        d_Cv[j+1] = M.y + __logf(S.y);
        d_Cv[j+2] = M.z + __logf(S.z);
        d_Cv[j+3] = M.w + __logf(S.w);
    }
}

// T[b,j] = sum_i exp(Z - R - C)  (args <= 0, plain sum), vectorized like k_col_lse
__global__ void k_col_T(const float* __restrict__ Z){
    int b     = blockIdx.x >> 3;
    int chunk = blockIdx.x & 7;
    int cg    = threadIdx.x & 31;
    int rg    = threadIdx.x >> 5;
    __shared__ float rs[NNODE];
    for (int k=threadIdx.x; k<NNODE; k+=256) rs[k] = d_Rv[b*NNODE + k];
    __syncthreads();
    float4 cj = *((const float4*)(d_Cv + b*NNODE) + chunk*32 + cg);
    const float4* z = (const float4*)(Z + (size_t)b*NNODE*NNODE) + chunk*32 + cg;
    float4 s = {0.f,0.f,0.f,0.f};
    int i0 = rg*128;
    for (int i=i0; i<i0+128; i++){
        float4 v = z[(size_t)i*256];
        float r = rs[i];
        s.x += __expf(v.x - r - cj.x);
        s.y += __expf(v.y - r - cj.y);
        s.z += __expf(v.z - r - cj.z);
        s.w += __expf(v.w - r - cj.w);
    }
    __shared__ float4 ss8[8][32];
    ss8[rg][cg] = s;
    __syncthreads();
    if (rg == 0){
        float4 S = s;
        #pragma unroll
        for (int g=1; g<8; g++){
            float4 sg = ss8[g][cg];
            S.x += sg.x; S.y += sg.y; S.z += sg.z; S.w += sg.w;
        }
        int j = b*NNODE + chunk*128 + cg*4;
        d_Tv[j+0]=S.x; d_Tv[j+1]=S.y; d_Tv[j+2]=S.z; d_Tv[j+3]=S.w;
    }
}

__global__ void k_final(const float* __restrict__ Z, float* __restrict__ P){
    size_t t = (size_t)blockIdx.x*256 + threadIdx.x;
    int row = (int)(t >> 10);
    int b   = row >> 10;
    int j   = (int)(t & 1023);
    P[t] = __expf(Z[t] - d_Rv[row] - d_Cv[b*NNODE + j]) / d_Tv[b*NNODE + j];
}

extern "C" void kernel_launch(void* const* d_in, const int* in_sizes, int n_in,
                              void* d_out, int out_size) {
    const float* X      = (const float*)d_in[0];
    const float* adj    = (const float*)d_in[1];
    const float* w_in   = (const float*)d_in[2];
    const float* b_in   = (const float*)d_in[3];
    const float* cw1    = (const float*)d_in[4];
    const float* cb1    = (const float*)d_in[5];
    const float* cw2    = (const float*)d_in[6];
    const float* cb2    = (const float*)d_in[7];
    const float* ca     = (const float*)d_in[8];
    const float* m1w    = (const float*)d_in[9];
    const float* m1b    = (const float*)d_in[10];
    const float* m2w    = (const float*)d_in[11];
    const float* m2b    = (const float*)d_in[12];
    float* Pout = (float*)d_out;
    float* Z0   = Pout + (size_t)TOTEL;

    float *hid, *hs, *g, *u1, *u2, *u3, *u4, *hp, *mid, *lg;
    cudaGetSymbolAddress((void**)&hid, d_hid);
    cudaGetSymbolAddress((void**)&hs,  d_hs);
    cudaGetSymbolAddress((void**)&g,   d_g);
    cudaGetSymbolAddress((void**)&u1,  d_u1);
    cudaGetSymbolAddress((void**)&u2,  d_u2);
    cudaGetSymbolAddress((void**)&u3,  d_u3);
    cudaGetSymbolAddress((void**)&u4,  d_u4);
    cudaGetSymbolAddress((void**)&hp,  d_hp);
    cudaGetSymbolAddress((void**)&mid, d_mid);
    cudaGetSymbolAddress((void**)&lg,  d_logits);
    float *dis, *invdeg;
    cudaGetSymbolAddress((void**)&dis,    d_dis);
    cudaGetSymbolAddress((void**)&invdeg, d_invdeg);

    k_adj_stats<<<NROWS/8, 256>>>(adj);

    // h0 = X @ w_in^T + b_in
    k_gemm_nt<<<dim3(2,128), 256>>>(X, 128, w_in, 128, b_in, hid, 768, 0);

    dim3 bg(2, 8, 16);
    for (int l = 0; l < 2; l++){
        int off  = 256*l;
        int offn = 256*(l+1);
        k_scale_hs<<<NROWS*HD/256, 256>>>(off);
        k_bgemm<<<bg, 256>>>(adj, hs, 256, g,  256, 1, hs, 256, dis);
        k_bgemm<<<bg, 256>>>(adj, hid+off, 768, u1, 256, 2, hid+off, 768, invdeg);
        k_bgemm<<<bg, 256>>>(adj, u1, 256, u2, 256, 2, u1, 256, invdeg);
        k_bgemm<<<bg, 256>>>(adj, u2, 256, u3, 256, 2, u2, 256, invdeg);
        k_bgemm<<<bg, 256>>>(adj, u3, 256, u4, 256, 2, u3, 256, invdeg);
        k_attn<<<NROWS, 256>>>(off, ca + l*512);
        k_gemm_nt<<<dim3(2,128), 256>>>(hp,  256, cw1 + l*65536, 256, cb1 + l*256, mid, 256, 1);
        k_gemm_nt<<<dim3(2,128), 256>>>(mid, 256, cw2 + l*65536, 256, cb2 + l*256, hid + offn, 768, 1);
    }

    // mlp1 + mlp2
    k_gemm_nt<<<dim3(2,128), 256>>>(hid, 768, m1w, 768, m1b, mid, 256, 1);
    k_gemm_nt<<<dim3(8,128), 256>>>(mid, 256, m2w, 256, m2b, lg, 1024, 2);

    // Z0 = (logits + gumbel)/tau  (gsinit output)
    k_z0<<<TOTEL/256, 256>>>(Z0);

    // Sinkhorn: rank-1 log-domain state (R, C)
    k_zeroC<<<NROWS/256, 256>>>();
    for (int it = 0; it < 20; it++){
        k_row_lse<<<NROWS/8, 256>>>(Z0);
        k_col_lse<<<128, 256>>>(Z0);
    }
    k_row_lse<<<NROWS/8, 256>>>(Z0);
    k_col_T  <<<128, 256>>>(Z0);
    k_final  <<<TOTEL/256, 256>>>(Z0, Pout);
}

// round 11
// speedup vs baseline: 1.1497x; 1.1497x over previous
#include <cuda_runtime.h>
#include <cstdint>
#include <math.h>

#define NBATCH 16
#define NNODE  1024
#define HD     256
#define NROWS  (NBATCH*NNODE)
#define TOTEL  16777216

__device__ float d_hid[NROWS*768];
__device__ float d_hs [NROWS*HD];
__device__ float d_g  [NROWS*HD];
__device__ float d_u1 [NROWS*HD];
__device__ float d_u2 [NROWS*HD];
__device__ float d_u3 [NROWS*HD];
__device__ float d_u4 [NROWS*HD];
__device__ float d_hp [NROWS*HD];
__device__ float d_mid[NROWS*HD];
__device__ float d_logits[TOTEL];
__device__ float d_dis[NROWS];
__device__ float d_invdeg[NROWS];
__device__ float d_Rv[NROWS];
__device__ float d_Cv[NROWS];
__device__ float d_Tv[NROWS];

__device__ __forceinline__ float leakyf(float x){ return x > 0.f ? x : 0.01f*x; }

__global__ void k_adj_stats(const float* __restrict__ adj){
    int row  = blockIdx.x*8 + (threadIdx.x>>5);
    int lane = threadIdx.x & 31;
    const float* a = adj + (size_t)row*NNODE;
    float s = 0.f;
    #pragma unroll
    for (int k=0;k<32;k++) s += a[lane + 32*k];
    #pragma unroll
    for (int o=16;o;o>>=1) s += __shfl_xor_sync(0xffffffffu, s, o);
    if (lane==0){ d_dis[row] = rsqrtf(s + 1.f); d_invdeg[row] = 1.f/s; }
}

__global__ void k_scale_hs(int off){
    int idx = blockIdx.x*256 + threadIdx.x;
    int row = idx >> 8, col = idx & 255;
    d_hs[idx] = d_dis[row] * d_hid[(size_t)row*768 + off + col];
}

#define BM 128
#define BN 128
#define BK 16

// ---- shared GEMM mainloop body (macro to avoid divergence in duplication) ----
#define GEMM_MAINLOOP(APTR, BPTR, BSTRIDE, NTILE)                                            \
    float4 a0 = *(const float4*)(APTR);                                                      \
    float4 a1 = *(const float4*)(APTR + 4);                                                  \
    float4 b0 = *(const float4*)(BPTR);                                                      \
    float4 b1 = *(const float4*)(BPTR + 4);                                                  \
    As[0][acol+0][arow]=a0.x; As[0][acol+1][arow]=a0.y; As[0][acol+2][arow]=a0.z; As[0][acol+3][arow]=a0.w; \
    As[0][acol+4][arow]=a1.x; As[0][acol+5][arow]=a1.y; As[0][acol+6][arow]=a1.z; As[0][acol+7][arow]=a1.w; \
    *(float4*)&Bs[0][brow][bcol]   = b0;                                                     \
    *(float4*)&Bs[0][brow][bcol+4] = b1;                                                     \
    __syncthreads();                                                                         \
    for (int t = 0; t < (NTILE); t++){                                                       \
        int cur = t & 1;                                                                     \
        if (t+1 < (NTILE)){                                                                  \
            a0 = *(const float4*)((APTR) + (t+1)*BK);                                        \
            a1 = *(const float4*)((APTR) + (t+1)*BK + 4);                                    \
            b0 = *(const float4*)((BPTR) + (size_t)(t+1)*BK*(BSTRIDE));                      \
            b1 = *(const float4*)((BPTR) + (size_t)(t+1)*BK*(BSTRIDE) + 4);                  \
        }                                                                                    \
        _Pragma("unroll")                                                                    \
        for (int k=0;k<BK;k++){                                                              \
            float4 fa0 = *(const float4*)&As[cur][k][ty*4];                                  \
            float4 fa1 = *(const float4*)&As[cur][k][64+ty*4];                               \
            float4 fb0 = *(const float4*)&Bs[cur][k][tx*4];                                  \
            float4 fb1 = *(const float4*)&Bs[cur][k][64+tx*4];                               \
            float ar[8] = {fa0.x,fa0.y,fa0.z,fa0.w,fa1.x,fa1.y,fa1.z,fa1.w};                 \
            float br[8] = {fb0.x,fb0.y,fb0.z,fb0.w,fb1.x,fb1.y,fb1.z,fb1.w};                 \
            _Pragma("unroll")                                                                \
            for (int m=0;m<8;m++)                                                            \
                _Pragma("unroll")                                                            \
                for (int n=0;n<8;n++)                                                        \
                    acc[m][n] = fmaf(ar[m], br[n], acc[m][n]);                               \
        }                                                                                    \
        if (t+1 < (NTILE)){                                                                  \
            int nxt = cur ^ 1;                                                               \
            As[nxt][acol+0][arow]=a0.x; As[nxt][acol+1][arow]=a0.y; As[nxt][acol+2][arow]=a0.z; As[nxt][acol+3][arow]=a0.w; \
            As[nxt][acol+4][arow]=a1.x; As[nxt][acol+5][arow]=a1.y; As[nxt][acol+6][arow]=a1.z; As[nxt][acol+7][arow]=a1.w; \
            *(float4*)&Bs[nxt][brow][bcol]   = b0;                                           \
            *(float4*)&Bs[nxt][brow][bcol+4] = b1;                                           \
            __syncthreads();                                                                 \
        }                                                                                    \
    }

#define GEMM_ADJ_EPILOGUE(MODE, AUX, LDAUX, VEC, OUT, LDC)                                   \
    _Pragma("unroll")                                                                        \
    for (int mh=0; mh<2; mh++)                                                               \
    _Pragma("unroll")                                                                        \
    for (int mi=0; mi<4; mi++){                                                              \
        int m = mh*4+mi;                                                                     \
        size_t gi = (size_t)(bb*NNODE + m0 + mh*64 + ty*4 + mi);                             \
        float dv = (VEC)[gi];                                                                \
        const float* auxr = (AUX) + gi*(size_t)(LDAUX) + n0;                                 \
        float* outr = (OUT) + gi*(size_t)(LDC) + n0;                                         \
        _Pragma("unroll")                                                                    \
        for (int nh=0; nh<2; nh++){                                                          \
            int colb = nh*64 + tx*4;                                                         \
            float4 ax = *(const float4*)(auxr + colb);                                       \
            float4 o;                                                                        \
            if ((MODE) == 1){                                                                \
                o.x = leakyf(dv*(acc[m][nh*4+0]+ax.x));                                      \
                o.y = leakyf(dv*(acc[m][nh*4+1]+ax.y));                                      \
                o.z = leakyf(dv*(acc[m][nh*4+2]+ax.z));                                      \
                o.w = leakyf(dv*(acc[m][nh*4+3]+ax.w));                                      \
            } else {                                                                         \
                o.x = 0.5f*(ax.x + acc[m][nh*4+0]*dv);                                       \
                o.y = 0.5f*(ax.y + acc[m][nh*4+1]*dv);                                       \
                o.z = 0.5f*(ax.z + acc[m][nh*4+2]*dv);                                       \
                o.w = 0.5f*(ax.w + acc[m][nh*4+3]*dv);                                       \
            }                                                                                \
            *(float4*)(outr + colb) = o;                                                     \
        }                                                                                    \
    }

// batched adj GEMM (serial lazy-walk steps)
__global__ __launch_bounds__(256,2) void k_bgemm(
    const float* __restrict__ Aadj, const float* __restrict__ B, int ldb,
    float* __restrict__ Cc, int ldc, int mode,
    const float* __restrict__ aux, int ldaux, const float* __restrict__ vec)
{
    int bb = blockIdx.z;
    int n0 = blockIdx.x * BN;
    int m0 = blockIdx.y * BM;
    const float* Ab = Aadj + (size_t)bb*NNODE*NNODE;
    __shared__ float As[2][BK][BM];
    __shared__ float Bs[2][BK][BN];
    int tid  = threadIdx.x;
    int arow = tid >> 1;
    int acol = (tid & 1) * 8;
    int brow = tid >> 4;
    int bcol = (tid & 15) * 8;
    int ty = tid >> 4, tx = tid & 15;

    const float* aptr = Ab + (size_t)(m0+arow)*NNODE + acol;
    const float* bptr = B + (size_t)(bb*NNODE + brow)*ldb + n0 + bcol;
    float acc[8][8] = {};
    GEMM_MAINLOOP(aptr, bptr, ldb, NNODE/BK)
    GEMM_ADJ_EPILOGUE(mode, aux, ldaux, vec, Cc, ldc)
}

// fused launch: blockIdx.x 0-1 -> GCN (hs->g, mode1), 2-3 -> first lazy walk (h->u1, mode2)
__global__ __launch_bounds__(256,2) void k_bgemm_dual(
    const float* __restrict__ Aadj,
    const float* __restrict__ B1, float* __restrict__ C1, const float* __restrict__ vec1,
    const float* __restrict__ B2, int ldb2, float* __restrict__ C2, const float* __restrict__ vec2)
{
    int bb = blockIdx.z;
    int nb = blockIdx.x;
    int half = nb >> 1;
    int n0 = (nb & 1) * BN;
    int m0 = blockIdx.y * BM;
    const float* Ab = Aadj + (size_t)bb*NNODE*NNODE;
    __shared__ float As[2][BK][BM];
    __shared__ float Bs[2][BK][BN];
    int tid  = threadIdx.x;
    int arow = tid >> 1;
    int acol = (tid & 1) * 8;
    int brow = tid >> 4;
    int bcol = (tid & 15) * 8;
    int ty = tid >> 4, tx = tid & 15;

    const float* B   = half ? B2 : B1;
    int ldb          = half ? ldb2 : 256;
    const float* aptr = Ab + (size_t)(m0+arow)*NNODE + acol;
    const float* bptr = B + (size_t)(bb*NNODE + brow)*ldb + n0 + bcol;
    float acc[8][8] = {};
    GEMM_MAINLOOP(aptr, bptr, ldb, NNODE/BK)
    if (half == 0){
        GEMM_ADJ_EPILOGUE(1, B1, 256, vec1, C1, 256)
    } else {
        GEMM_ADJ_EPILOGUE(2, B2, ldb2, vec2, C2, 256)
    }
}

// dense NT GEMM, double-buffered, conflict-free split fragments
__global__ __launch_bounds__(256,2) void k_gemm_nt(
    const float* __restrict__ A, int lda,
    const float* __restrict__ W, int K, const float* __restrict__ bias,
    float* __restrict__ Cc, int ldc, int act)
{
    int n0 = blockIdx.x * BN;
    int m0 = blockIdx.y * BM;
    __shared__ float As[2][BK][BM];
    __shared__ float Bs[2][BK][BN];
    int tid  = threadIdx.x;
    int arow = tid >> 1;
    int acol = (tid & 1) * 8;
    int ty = tid >> 4, tx = tid & 15;

    const float* aptr = A + (size_t)(m0+arow)*lda + acol;
    const float* wptr = W + (size_t)(n0+arow)*K   + acol;

    float4 a0 = *(const float4*)(aptr);
    float4 a1 = *(const float4*)(aptr + 4);
    float4 w0 = *(const float4*)(wptr);
    float4 w1 = *(const float4*)(wptr + 4);
    As[0][acol+0][arow]=a0.x; As[0][acol+1][arow]=a0.y; As[0][acol+2][arow]=a0.z; As[0][acol+3][arow]=a0.w;
    As[0][acol+4][arow]=a1.x; As[0][acol+5][arow]=a1.y; As[0][acol+6][arow]=a1.z; As[0][acol+7][arow]=a1.w;
    Bs[0][acol+0][arow]=w0.x; Bs[0][acol+1][arow]=w0.y; Bs[0][acol+2][arow]=w0.z; Bs[0][acol+3][arow]=w0.w;
    Bs[0][acol+4][arow]=w1.x; Bs[0][acol+5][arow]=w1.y; Bs[0][acol+6][arow]=w1.z; Bs[0][acol+7][arow]=w1.w;
    __syncthreads();

    float acc[8][8] = {};
    const int ntile = K/BK;
    for (int t = 0; t < ntile; t++){
        int cur = t & 1;
        if (t+1 < ntile){
            a0 = *(const float4*)(aptr + (t+1)*BK);
            a1 = *(const float4*)(aptr + (t+1)*BK + 4);
            w0 = *(const float4*)(wptr + (t+1)*BK);
            w1 = *(const float4*)(wptr + (t+1)*BK + 4);
        }
        #pragma unroll
        for (int k=0;k<BK;k++){
            float4 fa0 = *(const float4*)&As[cur][k][ty*4];
            float4 fa1 = *(const float4*)&As[cur][k][64+ty*4];
            float4 fb0 = *(const float4*)&Bs[cur][k][tx*4];
            float4 fb1 = *(const float4*)&Bs[cur][k][64+tx*4];
            float ar[8] = {fa0.x,fa0.y,fa0.z,fa0.w,fa1.x,fa1.y,fa1.z,fa1.w};
            float br[8] = {fb0.x,fb0.y,fb0.z,fb0.w,fb1.x,fb1.y,fb1.z,fb1.w};
            #pragma unroll
            for (int m=0;m<8;m++)
                #pragma unroll
                for (int n=0;n<8;n++)
                    acc[m][n] = fmaf(ar[m], br[n], acc[m][n]);
        }
        if (t+1 < ntile){
            int nxt = cur ^ 1;
            As[nxt][acol+0][arow]=a0.x; As[nxt][acol+1][arow]=a0.y; As[nxt][acol+2][arow]=a0.z; As[nxt][acol+3][arow]=a0.w;
            As[nxt][acol+4][arow]=a1.x; As[nxt][acol+5][arow]=a1.y; As[nxt][acol+6][arow]=a1.z; As[nxt][acol+7][arow]=a1.w;
            Bs[nxt][acol+0][arow]=w0.x; Bs[nxt][acol+1][arow]=w0.y; Bs[nxt][acol+2][arow]=w0.z; Bs[nxt][acol+3][arow]=w0.w;
            Bs[nxt][acol+4][arow]=w1.x; Bs[nxt][acol+5][arow]=w1.y; Bs[nxt][acol+6][arow]=w1.z; Bs[nxt][acol+7][arow]=w1.w;
            __syncthreads();
        }
    }
    #pragma unroll
    for (int mh=0; mh<2; mh++)
    #pragma unroll
    for (int mi=0; mi<4; mi++){
        int m = mh*4+mi;
        size_t gi = (size_t)(m0 + mh*64 + ty*4 + mi);
        float* outr = Cc + gi*(size_t)ldc + n0;
        #pragma unroll
        for (int nh=0; nh<2; nh++){
            int colb = nh*64 + tx*4;
            float4 bs = *(const float4*)(bias + n0 + colb);
            float4 o;
            o.x = acc[m][nh*4+0] + bs.x;
            o.y = acc[m][nh*4+1] + bs.y;
            o.z = acc[m][nh*4+2] + bs.z;
            o.w = acc[m][nh*4+3] + bs.w;
            if (act == 1){
                o.x=leakyf(o.x); o.y=leakyf(o.y); o.z=leakyf(o.z); o.w=leakyf(o.w);
            } else if (act == 2){
                o.x=tanhf(o.x)*40.f; o.y=tanhf(o.y)*40.f; o.z=tanhf(o.z)*40.f; o.w=tanhf(o.w)*40.f;
            }
            *(float4*)(outr + colb) = o;
        }
    }
}

// channel attention + weighted mean over 4 channels
__global__ void k_attn(int off, const float* __restrict__ avec){
    int i = blockIdx.x, d = threadIdx.x;
    size_t b = (size_t)i*HD + d;
    float x  = d_hid[(size_t)i*768 + off + d];
    float c0 = d_g[b];
    float u1 = d_u1[b], u2 = d_u2[b], u4 = d_u4[b];
    float c1 = fabsf(x - u1), c2 = fabsf(u1 - u2), c3 = fabsf(u2 - u4);
    float ah = avec[256 + d];
    float e0 = fmaxf(c0, 0.f)*ah, e1 = c1*ah, e2 = c2*ah, e3 = c3*ah;
    #pragma unroll
    for (int o=16;o;o>>=1){
        e0 += __shfl_xor_sync(0xffffffffu, e0, o);
        e1 += __shfl_xor_sync(0xffffffffu, e1, o);
        e2 += __shfl_xor_sync(0xffffffffu, e2, o);
        e3 += __shfl_xor_sync(0xffffffffu, e3, o);
    }
    __shared__ float sred[4][8];
    __shared__ float tot[4];
    int w = d >> 5;
    if ((d & 31) == 0){ sred[0][w]=e0; sred[1][w]=e1; sred[2][w]=e2; sred[3][w]=e3; }
    __syncthreads();
    if (d < 4){
        float t = 0.f;
        #pragma unroll
        for (int ww=0; ww<8; ww++) t += sred[d][ww];
        tot[d] = t;
    }
    __syncthreads();
    float E0=tot[0], E1=tot[1], E2=tot[2], E3=tot[3];
    float m = fmaxf(fmaxf(E0,E1), fmaxf(E2,E3));
    float w0=__expf(E0-m), w1=__expf(E1-m), w2=__expf(E2-m), w3=__expf(E3-m);
    float inv = 0.25f / (w0+w1+w2+w3);
    d_hp[b] = inv * (w0*c0 + w1*c1 + w2*c2 + w3*c3);
}

// Threefry-2x32-20, key (0,42)
__device__ __forceinline__ void threefry(unsigned x0, unsigned x1, unsigned& o0, unsigned& o1){
    const unsigned ks0 = 0u, ks1 = 42u, ks2 = 0x1BD11BDAu ^ 42u;
    x0 += ks0; x1 += ks1;
#define TFR(r) { x0 += x1; x1 = (x1<<(r))|(x1>>(32-(r))); x1 ^= x0; }
    TFR(13) TFR(15) TFR(26) TFR(6)   x0+=ks1; x1+=ks2+1u;
    TFR(17) TFR(29) TFR(16) TFR(24)  x0+=ks2; x1+=ks0+2u;
    TFR(13) TFR(15) TFR(26) TFR(6)   x0+=ks0; x1+=ks1+3u;
    TFR(17) TFR(29) TFR(16) TFR(24)  x0+=ks1; x1+=ks2+4u;
    TFR(13) TFR(15) TFR(26) TFR(6)   x0+=ks2; x1+=ks0+5u;
#undef TFR
    o0 = x0; o1 = x1;
}

__device__ __forceinline__ float gumb(unsigned bits){
    float u = __uint_as_float((bits >> 9) | 0x3F800000u) - 1.0f;
    return -logf(-logf(u + 1e-20f) + 1e-20f) * 0.05f;
}

// JAX partitionable threefry: counter = uint64 t -> (hi=0, lo=t), out = o0^o1
__global__ void k_z0(float* __restrict__ z0){
    unsigned t = blockIdx.x*256u + threadIdx.x;
    unsigned o0, o1;
    threefry(0u, t, o0, o1);
    z0[t] = (d_logits[t] + gumb(o0 ^ o1)) * 10.0f;
}

__global__ void k_zeroC(){ d_Cv[blockIdx.x*256 + threadIdx.x] = 0.f; }

// R[row] = lse_j(Z[row,:] - C[b,:]); one warp per row
__global__ void k_row_lse(const float* __restrict__ Z){
    int row  = blockIdx.x*8 + (threadIdx.x>>5);
    int lane = threadIdx.x & 31;
    int b    = row >> 10;
    const float* z = Z + (size_t)row*NNODE;
    const float* c = d_Cv + b*NNODE;
    float v[32];
    float m = -3.4e38f;
    #pragma unroll
    for (int k=0;k<32;k++){ v[k] = z[lane + 32*k] - c[lane + 32*k]; m = fmaxf(m, v[k]); }
    #pragma unroll
    for (int o=16;o;o>>=1) m = fmaxf(m, __shfl_xor_sync(0xffffffffu, m, o));
    float s = 0.f;
    #pragma unroll
    for (int k=0;k<32;k++) s += __expf(v[k] - m);
    #pragma unroll
    for (int o=16;o;o>>=1) s += __shfl_xor_sync(0xffffffffu, s, o);
    if (lane==0) d_Rv[row] = m + __logf(s);
}

__device__ __forceinline__ void online_lse(float v, float& m, float& s){
    if (v > m){ s = s*__expf(m - v) + 1.f; m = v; }
    else      { s += __expf(v - m); }
}
__device__ __forceinline__ void merge_lse(float& M, float& S, float mg, float sg){
    if (mg > M){ S = S*__expf(M - mg) + sg; M = mg; }
    else       { S += sg*__expf(mg - M); }
}

// C[b,j] = lse_i(Z[b,i,j] - R[b,i])
// grid = 16 batches x 16 chunks(64 cols); block 256 = 16 colgroups(float4) x 16 rowgroups(64 rows)
// 4 independent online states per lane component, 8-deep load batches for MLP
__global__ void k_col_lse(const float* __restrict__ Z){
    int b     = blockIdx.x >> 4;
    int chunk = blockIdx.x & 15;
    int cg    = threadIdx.x & 15;
    int rg    = threadIdx.x >> 4;
    __shared__ float rs[NNODE];
    for (int k=threadIdx.x; k<NNODE; k+=256) rs[k] = d_Rv[b*NNODE + k];
    __syncthreads();
    const float4* z = (const float4*)(Z + (size_t)b*NNODE*NNODE) + chunk*16 + cg;
    float4 m[4], s[4];
    #pragma unroll
    for (int j=0;j<4;j++){
        m[j] = make_float4(-3.4e38f,-3.4e38f,-3.4e38f,-3.4e38f);
        s[j] = make_float4(0.f,0.f,0.f,0.f);
    }
    int i0 = rg*64;
    for (int i=i0; i<i0+64; i+=8){
        float4 v[8]; float r[8];
        #pragma unroll
        for (int j=0;j<8;j++){ v[j] = z[(size_t)(i+j)*256]; r[j] = rs[i+j]; }
        #pragma unroll
        for (int j=0;j<8;j++){
            int st = j & 3;
            online_lse(v[j].x - r[j], m[st].x, s[st].x);
            online_lse(v[j].y - r[j], m[st].y, s[st].y);
            online_lse(v[j].z - r[j], m[st].z, s[st].z);
            online_lse(v[j].w - r[j], m[st].w, s[st].w);
        }
    }
    float4 M = m[0], S = s[0];
    #pragma unroll
    for (int j=1;j<4;j++){
        merge_lse(M.x, S.x, m[j].x, s[j].x);
        merge_lse(M.y, S.y, m[j].y, s[j].y);
        merge_lse(M.z, S.z, m[j].z, s[j].z);
        merge_lse(M.w, S.w, m[j].w, s[j].w);
    }
    __shared__ float4 sm16[16][16], ss16[16][16];
    sm16[rg][cg] = M; ss16[rg][cg] = S;
    __syncthreads();
    if (rg == 0){
        #pragma unroll
        for (int g=1; g<16; g++){
            float4 mg = sm16[g][cg], sg = ss16[g][cg];
            merge_lse(M.x, S.x, mg.x, sg.x);
            merge_lse(M.y, S.y, mg.y, sg.y);
            merge_lse(M.z, S.z, mg.z, sg.z);
            merge_lse(M.w, S.w, mg.w, sg.w);
        }
        int j = b*NNODE + chunk*64 + cg*4;
        d_Cv[j+0] = M.x + __logf(S.x);
        d_Cv[j+1] = M.y + __logf(S.y);
        d_Cv[j+2] = M.z + __logf(S.z);
        d_Cv[j+3] = M.w + __logf(S.w);
    }
}

// T[b,j] = sum_i exp(Z - R - C), same layout as k_col_lse
__global__ void k_col_T(const float* __restrict__ Z){
    int b     = blockIdx.x >> 4;
    int chunk = blockIdx.x & 15;
    int cg    = threadIdx.x & 15;
    int rg    = threadIdx.x >> 4;
    __shared__ float rs[NNODE];
    for (int k=threadIdx.x; k<NNODE; k+=256) rs[k] = d_Rv[b*NNODE + k];
    __syncthreads();
    float4 cj = *((const float4*)(d_Cv + b*NNODE) + chunk*16 + cg);
    const float4* z = (const float4*)(Z + (size_t)b*NNODE*NNODE) + chunk*16 + cg;
    float4 s = {0.f,0.f,0.f,0.f};
    int i0 = rg*64;
    for (int i=i0; i<i0+64; i+=8){
        float4 v[8]; float r[8];
        #pragma unroll
        for (int j=0;j<8;j++){ v[j] = z[(size_t)(i+j)*256]; r[j] = rs[i+j]; }
        #pragma unroll
        for (int j=0;j<8;j++){
            s.x += __expf(v[j].x - r[j] - cj.x);
            s.y += __expf(v[j].y - r[j] - cj.y);
            s.z += __expf(v[j].z - r[j] - cj.z);
            s.w += __expf(v[j].w - r[j] - cj.w);
        }
    }
    __shared__ float4 ss16[16][16];
    ss16[rg][cg] = s;
    __syncthreads();
    if (rg == 0){
        #pragma unroll
        for (int g=1; g<16; g++){
            float4 sg = ss16[g][cg];
            s.x += sg.x; s.y += sg.y; s.z += sg.z; s.w += sg.w;
        }
        int j = b*NNODE + chunk*64 + cg*4;
        d_Tv[j+0]=s.x; d_Tv[j+1]=s.y; d_Tv[j+2]=s.z; d_Tv[j+3]=s.w;
    }
}

__global__ void k_final(const float* __restrict__ Z, float* __restrict__ P){
    size_t t = (size_t)blockIdx.x*256 + threadIdx.x;
    int row = (int)(t >> 10);
    int b   = row >> 10;
    int j   = (int)(t & 1023);
    P[t] = __expf(Z[t] - d_Rv[row] - d_Cv[b*NNODE + j]) / d_Tv[b*NNODE + j];
}

extern "C" void kernel_launch(void* const* d_in, const int* in_sizes, int n_in,
                              void* d_out, int out_size) {
    const float* X      = (const float*)d_in[0];
    const float* adj    = (const float*)d_in[1];
    const float* w_in   = (const float*)d_in[2];
    const float* b_in   = (const float*)d_in[3];
    const float* cw1    = (const float*)d_in[4];
    const float* cb1    = (const float*)d_in[5];
    const float* cw2    = (const float*)d_in[6];
    const float* cb2    = (const float*)d_in[7];
    const float* ca     = (const float*)d_in[8];
    const float* m1w    = (const float*)d_in[9];
    const float* m1b    = (const float*)d_in[10];
    const float* m2w    = (const float*)d_in[11];
    const float* m2b    = (const float*)d_in[12];
    float* Pout = (float*)d_out;
    float* Z0   = Pout + (size_t)TOTEL;

    float *hid, *hs, *g, *u1, *u2, *u3, *u4, *hp, *mid, *lg;
    cudaGetSymbolAddress((void**)&hid, d_hid);
    cudaGetSymbolAddress((void**)&hs,  d_hs);
    cudaGetSymbolAddress((void**)&g,   d_g);
    cudaGetSymbolAddress((void**)&u1,  d_u1);
    cudaGetSymbolAddress((void**)&u2,  d_u2);
    cudaGetSymbolAddress((void**)&u3,  d_u3);
    cudaGetSymbolAddress((void**)&u4,  d_u4);
    cudaGetSymbolAddress((void**)&hp,  d_hp);
    cudaGetSymbolAddress((void**)&mid, d_mid);
    cudaGetSymbolAddress((void**)&lg,  d_logits);
    float *dis, *invdeg;
    cudaGetSymbolAddress((void**)&dis,    d_dis);
    cudaGetSymbolAddress((void**)&invdeg, d_invdeg);

    k_adj_stats<<<NROWS/8, 256>>>(adj);

    // h0 = X @ w_in^T + b_in
    k_gemm_nt<<<dim3(2,128), 256>>>(X, 128, w_in, 128, b_in, hid, 768, 0);

    dim3 bg(2, 8, 16);
    dim3 bgd(4, 8, 16);
    for (int l = 0; l < 2; l++){
        int off  = 256*l;
        int offn = 256*(l+1);
        k_scale_hs<<<NROWS*HD/256, 256>>>(off);
        // fused: g = leaky(GCN), u1 = first lazy-walk step
        k_bgemm_dual<<<bgd, 256>>>(adj, hs, g, dis, hid+off, 768, u1, invdeg);
        k_bgemm<<<bg, 256>>>(adj, u1, 256, u2, 256, 2, u1, 256, invdeg);
        k_bgemm<<<bg, 256>>>(adj, u2, 256, u3, 256, 2, u2, 256, invdeg);
        k_bgemm<<<bg, 256>>>(adj, u3, 256, u4, 256, 2, u3, 256, invdeg);
        k_attn<<<NROWS, 256>>>(off, ca + l*512);
        k_gemm_nt<<<dim3(2,128), 256>>>(hp,  256, cw1 + l*65536, 256, cb1 + l*256, mid, 256, 1);
        k_gemm_nt<<<dim3(2,128), 256>>>(mid, 256, cw2 + l*65536, 256, cb2 + l*256, hid + offn, 768, 1);
    }

    // mlp1 + mlp2
    k_gemm_nt<<<dim3(2,128), 256>>>(hid, 768, m1w, 768, m1b, mid, 256, 1);
    k_gemm_nt<<<dim3(8,128), 256>>>(mid, 256, m2w, 256, m2b, lg, 1024, 2);

    // Z0 = (logits + gumbel)/tau  (gsinit output)
    k_z0<<<TOTEL/256, 256>>>(Z0);

    // Sinkhorn: rank-1 log-domain state (R, C)
    k_zeroC<<<NROWS/256, 256>>>();
    for (int it = 0; it < 20; it++){
        k_row_lse<<<NROWS/8, 256>>>(Z0);
        k_col_lse<<<256, 256>>>(Z0);
    }
    k_row_lse<<<NROWS/8, 256>>>(Z0);
    k_col_T  <<<256, 256>>>(Z0);
    k_final  <<<TOTEL/256, 256>>>(Z0, Pout);
}

// round 13
// speedup vs baseline: 1.2267x; 1.0670x over previous
#include <cuda_runtime.h>
#include <cuda_bf16.h>
#include <cstdint>
#include <math.h>

#define NBATCH 16
#define NNODE  1024
#define HD     256
#define NROWS  (NBATCH*NNODE)
#define TOTEL  16777216

__device__ float d_hid[NROWS*768];
__device__ float d_hs [NROWS*HD];
__device__ float d_g  [NROWS*HD];
__device__ float d_u1 [NROWS*HD];
__device__ float d_u2 [NROWS*HD];
__device__ float d_u3 [NROWS*HD];
__device__ float d_u4 [NROWS*HD];
__device__ float d_hp [NROWS*HD];
__device__ float d_mid[NROWS*HD];
__device__ float d_logits[TOTEL];
__device__ float d_dis[NROWS];
__device__ float d_invdeg[NROWS];
__device__ float d_Rv[NROWS];
__device__ float d_Cv[NROWS];
__device__ float d_Tv[NROWS];

__device__ __forceinline__ float leakyf(float x){ return x > 0.f ? x : 0.01f*x; }

__global__ void k_adj_stats(const float* __restrict__ adj){
    int row  = blockIdx.x*8 + (threadIdx.x>>5);
    int lane = threadIdx.x & 31;
    const float* a = adj + (size_t)row*NNODE;
    float s = 0.f;
    #pragma unroll
    for (int k=0;k<32;k++) s += a[lane + 32*k];
    #pragma unroll
    for (int o=16;o;o>>=1) s += __shfl_xor_sync(0xffffffffu, s, o);
    if (lane==0){ d_dis[row] = rsqrtf(s + 1.f); d_invdeg[row] = 1.f/s; }
}

__global__ void k_scale_hs(int off){
    int idx = blockIdx.x*256 + threadIdx.x;
    int row = idx >> 8, col = idx & 255;
    d_hs[idx] = d_dis[row] * d_hid[(size_t)row*768 + off + col];
}

// ---------------- 3xTF32 mma.sync helpers ----------------
__device__ __forceinline__ void split_tf32(float v, uint32_t& hi, uint32_t& lo){
    uint32_t h;
    asm("cvt.rna.tf32.f32 %0, %1;" : "=r"(h) : "f"(v));
    float r = v - __uint_as_float(h);
    uint32_t l;
    asm("cvt.rna.tf32.f32 %0, %1;" : "=r"(l) : "f"(r));
    hi = h; lo = l;
}
__device__ __forceinline__ void mma_tf32(float* c,
    uint32_t a0, uint32_t a1, uint32_t a2, uint32_t a3,
    uint32_t b0, uint32_t b1){
    asm volatile(
        "mma.sync.aligned.m16n8k8.row.col.f32.tf32.tf32.f32 "
        "{%0,%1,%2,%3}, {%4,%5,%6,%7}, {%8,%9}, {%0,%1,%2,%3};"
        : "+f"(c[0]), "+f"(c[1]), "+f"(c[2]), "+f"(c[3])
        : "r"(a0), "r"(a1), "r"(a2), "r"(a3), "r"(b0), "r"(b1));
}

// ---------------- batched adj GEMM on tensor cores (3xTF32) ----------------
// out[m][n] = epilogue( sum_k adj[b][m][k] * B[b][k][n] )
// mode1: out=leaky(dis*(acc+aux)); mode2: out=0.5*(aux+acc*invdeg)
#define PAD 132
__global__ __launch_bounds__(256,2) void k_mma(
    const float* __restrict__ Aadj, const float* __restrict__ B, int ldb,
    float* __restrict__ Cc, int mode,
    const float* __restrict__ aux, int ldaux, const float* __restrict__ vec)
{
    int bb = blockIdx.z;
    int n0 = blockIdx.x * 128;
    int m0 = blockIdx.y * 128;
    const float* Ab = Aadj + (size_t)bb*NNODE*NNODE;
    __shared__ float As[2][16][PAD];
    __shared__ float Bs[2][16][PAD];
    int tid  = threadIdx.x;
    int wid  = tid >> 5, lane = tid & 31;
    int lr = lane >> 2, lc = lane & 3;
    int wm = (wid & 3) * 32;
    int wn = (wid >> 2) * 64;
    int arow = tid >> 1, acol = (tid & 1)*8;
    int brow = tid >> 4, bcol = (tid & 15)*8;

    const float* aptr = Ab + (size_t)(m0+arow)*NNODE + acol;
    const float* bptr = B + (size_t)(bb*NNODE + brow)*ldb + n0 + bcol;

    {
        float4 a0 = *(const float4*)(aptr);
        float4 a1 = *(const float4*)(aptr + 4);
        float4 b0 = *(const float4*)(bptr);
        float4 b1 = *(const float4*)(bptr + 4);
        As[0][acol+0][arow]=a0.x; As[0][acol+1][arow]=a0.y; As[0][acol+2][arow]=a0.z; As[0][acol+3][arow]=a0.w;
        As[0][acol+4][arow]=a1.x; As[0][acol+5][arow]=a1.y; As[0][acol+6][arow]=a1.z; As[0][acol+7][arow]=a1.w;
        *(float4*)&Bs[0][brow][bcol]   = b0;
        *(float4*)&Bs[0][brow][bcol+4] = b1;
    }
    __syncthreads();

    float acc[2][8][4] = {};
    const int ntile = NNODE/16;
    for (int t = 0; t < ntile; t++){
        int cur = t & 1;
        float4 pa0, pa1, pb0, pb1;
        if (t+1 < ntile){
            pa0 = *(const float4*)(aptr + (t+1)*16);
            pa1 = *(const float4*)(aptr + (t+1)*16 + 4);
            pb0 = *(const float4*)(bptr + (size_t)(t+1)*16*ldb);
            pb1 = *(const float4*)(bptr + (size_t)(t+1)*16*ldb + 4);
        }
        #pragma unroll
        for (int k8 = 0; k8 < 16; k8 += 8){
            uint32_t ahi[2][4], alo[2][4];
            #pragma unroll
            for (int f = 0; f < 2; f++){
                int mb = wm + f*16 + lr;
                float v0 = As[cur][k8+lc][mb];
                float v1 = As[cur][k8+lc][mb+8];
                float v2 = As[cur][k8+lc+4][mb];
                float v3 = As[cur][k8+lc+4][mb+8];
                split_tf32(v0, ahi[f][0], alo[f][0]);
                split_tf32(v1, ahi[f][1], alo[f][1]);
                split_tf32(v2, ahi[f][2], alo[f][2]);
                split_tf32(v3, ahi[f][3], alo[f][3]);
            }
            #pragma unroll
            for (int gh = 0; gh < 2; gh++){
                uint32_t bhi[4][2], blo[4][2];
                #pragma unroll
                for (int g = 0; g < 4; g++){
                    int n = wn + gh*32 + g*8 + lr;
                    split_tf32(Bs[cur][k8+lc][n],   bhi[g][0], blo[g][0]);
                    split_tf32(Bs[cur][k8+lc+4][n], bhi[g][1], blo[g][1]);
                }
                #pragma unroll
                for (int f = 0; f < 2; f++)
                #pragma unroll
                for (int g = 0; g < 4; g++){
                    float* c = acc[f][gh*4+g];
                    mma_tf32(c, ahi[f][0],ahi[f][1],ahi[f][2],ahi[f][3], bhi[g][0],bhi[g][1]);
                    mma_tf32(c, ahi[f][0],ahi[f][1],ahi[f][2],ahi[f][3], blo[g][0],blo[g][1]);
                    mma_tf32(c, alo[f][0],alo[f][1],alo[f][2],alo[f][3], bhi[g][0],bhi[g][1]);
                }
            }
        }
        if (t+1 < ntile){
            int nxt = cur ^ 1;
            As[nxt][acol+0][arow]=pa0.x; As[nxt][acol+1][arow]=pa0.y; As[nxt][acol+2][arow]=pa0.z; As[nxt][acol+3][arow]=pa0.w;
            As[nxt][acol+4][arow]=pa1.x; As[nxt][acol+5][arow]=pa1.y; As[nxt][acol+6][arow]=pa1.z; As[nxt][acol+7][arow]=pa1.w;
            *(float4*)&Bs[nxt][brow][bcol]   = pb0;
            *(float4*)&Bs[nxt][brow][bcol+4] = pb1;
            __syncthreads();
        }
    }

    // epilogue: acc frag (f,g): rows m0+wm+f*16+lr (+8), cols n0+wn+g*8+lc*2 (+1)
    #pragma unroll
    for (int f = 0; f < 2; f++){
        int r0 = m0 + wm + f*16 + lr;
        size_t gi0 = (size_t)(bb*NNODE + r0);
        size_t gi1 = gi0 + 8;
        float dv0 = vec[gi0], dv1 = vec[gi1];
        const float* aux0 = aux + gi0*(size_t)ldaux + n0 + wn;
        const float* aux1 = aux + gi1*(size_t)ldaux + n0 + wn;
        float* out0 = Cc + gi0*(size_t)256 + n0 + wn;
        float* out1 = Cc + gi1*(size_t)256 + n0 + wn;
        #pragma unroll
        for (int g = 0; g < 8; g++){
            int c = g*8 + lc*2;
            float2 ax0 = *(const float2*)(aux0 + c);
            float2 ax1 = *(const float2*)(aux1 + c);
            float* a = acc[f][g];
            float2 o0, o1;
            if (mode == 1){
                o0.x = leakyf(dv0*(a[0]+ax0.x)); o0.y = leakyf(dv0*(a[1]+ax0.y));
                o1.x = leakyf(dv1*(a[2]+ax1.x)); o1.y = leakyf(dv1*(a[3]+ax1.y));
            } else {
                o0.x = 0.5f*(ax0.x + a[0]*dv0); o0.y = 0.5f*(ax0.y + a[1]*dv0);
                o1.x = 0.5f*(ax1.x + a[2]*dv1); o1.y = 0.5f*(ax1.y + a[3]*dv1);
            }
            *(float2*)(out0 + c) = o0;
            *(float2*)(out1 + c) = o1;
        }
    }
}

// dense NT GEMM (SIMT)
#define BM 128
#define BN 128
#define BK 16
__global__ __launch_bounds__(256,2) void k_gemm_nt(
    const float* __restrict__ A, int lda,
    const float* __restrict__ W, int K, const float* __restrict__ bias,
    float* __restrict__ Cc, int ldc, int act)
{
    int n0 = blockIdx.x * BN;
    int m0 = blockIdx.y * BM;
    __shared__ float As[2][BK][BM];
    __shared__ float Bs[2][BK][BN];
    int tid  = threadIdx.x;
    int arow = tid >> 1;
    int acol = (tid & 1) * 8;
    int ty = tid >> 4, tx = tid & 15;

    const float* aptr = A + (size_t)(m0+arow)*lda + acol;
    const float* wptr = W + (size_t)(n0+arow)*K   + acol;

    float4 a0 = *(const float4*)(aptr);
    float4 a1 = *(const float4*)(aptr + 4);
    float4 w0 = *(const float4*)(wptr);
    float4 w1 = *(const float4*)(wptr + 4);
    As[0][acol+0][arow]=a0.x; As[0][acol+1][arow]=a0.y; As[0][acol+2][arow]=a0.z; As[0][acol+3][arow]=a0.w;
    As[0][acol+4][arow]=a1.x; As[0][acol+5][arow]=a1.y; As[0][acol+6][arow]=a1.z; As[0][acol+7][arow]=a1.w;
    Bs[0][acol+0][arow]=w0.x; Bs[0][acol+1][arow]=w0.y; Bs[0][acol+2][arow]=w0.z; Bs[0][acol+3][arow]=w0.w;
    Bs[0][acol+4][arow]=w1.x; Bs[0][acol+5][arow]=w1.y; Bs[0][acol+6][arow]=w1.z; Bs[0][acol+7][arow]=w1.w;
    __syncthreads();

    float acc[8][8] = {};
    const int ntile = K/BK;
    for (int t = 0; t < ntile; t++){
        int cur = t & 1;
        if (t+1 < ntile){
            a0 = *(const float4*)(aptr + (t+1)*BK);
            a1 = *(const float4*)(aptr + (t+1)*BK + 4);
            w0 = *(const float4*)(wptr + (t+1)*BK);
            w1 = *(const float4*)(wptr + (t+1)*BK + 4);
        }
        #pragma unroll
        for (int k=0;k<BK;k++){
            float4 fa0 = *(const float4*)&As[cur][k][ty*4];
            float4 fa1 = *(const float4*)&As[cur][k][64+ty*4];
            float4 fb0 = *(const float4*)&Bs[cur][k][tx*4];
            float4 fb1 = *(const float4*)&Bs[cur][k][64+tx*4];
            float ar[8] = {fa0.x,fa0.y,fa0.z,fa0.w,fa1.x,fa1.y,fa1.z,fa1.w};
            float br[8] = {fb0.x,fb0.y,fb0.z,fb0.w,fb1.x,fb1.y,fb1.z,fb1.w};
            #pragma unroll
            for (int m=0;m<8;m++)
                #pragma unroll
                for (int n=0;n<8;n++)
                    acc[m][n] = fmaf(ar[m], br[n], acc[m][n]);
        }
        if (t+1 < ntile){
            int nxt = cur ^ 1;
            As[nxt][acol+0][arow]=a0.x; As[nxt][acol+1][arow]=a0.y; As[nxt][acol+2][arow]=a0.z; As[nxt][acol+3][arow]=a0.w;
            As[nxt][acol+4][arow]=a1.x; As[nxt][acol+5][arow]=a1.y; As[nxt][acol+6][arow]=a1.z; As[nxt][acol+7][arow]=a1.w;
            Bs[nxt][acol+0][arow]=w0.x; Bs[nxt][acol+1][arow]=w0.y; Bs[nxt][acol+2][arow]=w0.z; Bs[nxt][acol+3][arow]=w0.w;
            Bs[nxt][acol+4][arow]=w1.x; Bs[nxt][acol+5][arow]=w1.y; Bs[nxt][acol+6][arow]=w1.z; Bs[nxt][acol+7][arow]=w1.w;
            __syncthreads();
        }
    }
    #pragma unroll
    for (int mh=0; mh<2; mh++)
    #pragma unroll
    for (int mi=0; mi<4; mi++){
        int m = mh*4+mi;
        size_t gi = (size_t)(m0 + mh*64 + ty*4 + mi);
        float* outr = Cc + gi*(size_t)ldc + n0;
        #pragma unroll
        for (int nh=0; nh<2; nh++){
            int colb = nh*64 + tx*4;
            float4 bs = *(const float4*)(bias + n0 + colb);
            float4 o;
            o.x = acc[m][nh*4+0] + bs.x;
            o.y = acc[m][nh*4+1] + bs.y;
            o.z = acc[m][nh*4+2] + bs.z;
            o.w = acc[m][nh*4+3] + bs.w;
            if (act == 1){
                o.x=leakyf(o.x); o.y=leakyf(o.y); o.z=leakyf(o.z); o.w=leakyf(o.w);
            } else if (act == 2){
                o.x=tanhf(o.x)*40.f; o.y=tanhf(o.y)*40.f; o.z=tanhf(o.z)*40.f; o.w=tanhf(o.w)*40.f;
            }
            *(float4*)(outr + colb) = o;
        }
    }
}

// channel attention + weighted mean over 4 channels
__global__ void k_attn(int off, const float* __restrict__ avec){
    int i = blockIdx.x, d = threadIdx.x;
    size_t b = (size_t)i*HD + d;
    float x  = d_hid[(size_t)i*768 + off + d];
    float c0 = d_g[b];
    float u1 = d_u1[b], u2 = d_u2[b], u4 = d_u4[b];
    float c1 = fabsf(x - u1), c2 = fabsf(u1 - u2), c3 = fabsf(u2 - u4);
    float ah = avec[256 + d];
    float e0 = fmaxf(c0, 0.f)*ah, e1 = c1*ah, e2 = c2*ah, e3 = c3*ah;
    #pragma unroll
    for (int o=16;o;o>>=1){
        e0 += __shfl_xor_sync(0xffffffffu, e0, o);
        e1 += __shfl_xor_sync(0xffffffffu, e1, o);
        e2 += __shfl_xor_sync(0xffffffffu, e2, o);
        e3 += __shfl_xor_sync(0xffffffffu, e3, o);
    }
    __shared__ float sred[4][8];
    __shared__ float tot[4];
    int w = d >> 5;
    if ((d & 31) == 0){ sred[0][w]=e0; sred[1][w]=e1; sred[2][w]=e2; sred[3][w]=e3; }
    __syncthreads();
    if (d < 4){
        float t = 0.f;
        #pragma unroll
        for (int ww=0; ww<8; ww++) t += sred[d][ww];
        tot[d] = t;
    }
    __syncthreads();
    float E0=tot[0], E1=tot[1], E2=tot[2], E3=tot[3];
    float m = fmaxf(fmaxf(E0,E1), fmaxf(E2,E3));
    float w0=__expf(E0-m), w1=__expf(E1-m), w2=__expf(E2-m), w3=__expf(E3-m);
    float inv = 0.25f / (w0+w1+w2+w3);
    d_hp[b] = inv * (w0*c0 + w1*c1 + w2*c2 + w3*c3);
}

// Threefry-2x32-20, key (0,42)
__device__ __forceinline__ void threefry(unsigned x0, unsigned x1, unsigned& o0, unsigned& o1){
    const unsigned ks0 = 0u, ks1 = 42u, ks2 = 0x1BD11BDAu ^ 42u;
    x0 += ks0; x1 += ks1;
#define TFR(r) { x0 += x1; x1 = (x1<<(r))|(x1>>(32-(r))); x1 ^= x0; }
    TFR(13) TFR(15) TFR(26) TFR(6)   x0+=ks1; x1+=ks2+1u;
    TFR(17) TFR(29) TFR(16) TFR(24)  x0+=ks2; x1+=ks0+2u;
    TFR(13) TFR(15) TFR(26) TFR(6)   x0+=ks0; x1+=ks1+3u;
    TFR(17) TFR(29) TFR(16) TFR(24)  x0+=ks1; x1+=ks2+4u;
    TFR(13) TFR(15) TFR(26) TFR(6)   x0+=ks2; x1+=ks0+5u;
#undef TFR
    o0 = x0; o1 = x1;
}

__device__ __forceinline__ float gumb(unsigned bits){
    float u = __uint_as_float((bits >> 9) | 0x3F800000u) - 1.0f;
    return -logf(-logf(u + 1e-20f) + 1e-20f) * 0.05f;
}

__global__ void k_z0(float* __restrict__ z0){
    unsigned t = blockIdx.x*256u + threadIdx.x;
    unsigned o0, o1;
    threefry(0u, t, o0, o1);
    z0[t] = (d_logits[t] + gumb(o0 ^ o1)) * 10.0f;
}

__global__ void k_zeroC(){ d_Cv[blockIdx.x*256 + threadIdx.x] = 0.f; }

__global__ void k_row_lse(const float* __restrict__ Z){
    int row  = blockIdx.x*8 + (threadIdx.x>>5);
    int lane = threadIdx.x & 31;
    int b    = row >> 10;
    const float* z = Z + (size_t)row*NNODE;
    const float* c = d_Cv + b*NNODE;
    float v[32];
    float m = -3.4e38f;
    #pragma unroll
    for (int k=0;k<32;k++){ v[k] = z[lane + 32*k] - c[lane + 32*k]; m = fmaxf(m, v[k]); }
    #pragma unroll
    for (int o=16;o;o>>=1) m = fmaxf(m, __shfl_xor_sync(0xffffffffu, m, o));
    float s = 0.f;
    #pragma unroll
    for (int k=0;k<32;k++) s += __expf(v[k] - m);
    #pragma unroll
    for (int o=16;o;o>>=1) s += __shfl_xor_sync(0xffffffffu, s, o);
    if (lane==0) d_Rv[row] = m + __logf(s);
}

__device__ __forceinline__ void online_lse(float v, float& m, float& s){
    if (v > m){ s = s*__expf(m - v) + 1.f; m = v; }
    else      { s += __expf(v - m); }
}
__device__ __forceinline__ void merge_lse(float& M, float& S, float mg, float sg){
    if (mg > M){ S = S*__expf(M - mg) + sg; M = mg; }
    else       { S += sg*__expf(mg - M); }
}

__global__ void k_col_lse(const float* __restrict__ Z){
    int b     = blockIdx.x >> 4;
    int chunk = blockIdx.x & 15;
    int cg    = threadIdx.x & 15;
    int rg    = threadIdx.x >> 4;
    __shared__ float rs[NNODE];
    for (int k=threadIdx.x; k<NNODE; k+=256) rs[k] = d_Rv[b*NNODE + k];
    __syncthreads();
    const float4* z = (const float4*)(Z + (size_t)b*NNODE*NNODE) + chunk*16 + cg;
    float4 m[4], s[4];
    #pragma unroll
    for (int j=0;j<4;j++){
        m[j] = make_float4(-3.4e38f,-3.4e38f,-3.4e38f,-3.4e38f);
        s[j] = make_float4(0.f,0.f,0.f,0.f);
    }
    int i0 = rg*64;
    for (int i=i0; i<i0+64; i+=8){
        float4 v[8]; float r[8];
        #pragma unroll
        for (int j=0;j<8;j++){ v[j] = z[(size_t)(i+j)*256]; r[j] = rs[i+j]; }
        #pragma unroll
        for (int j=0;j<8;j++){
            int st = j & 3;
            online_lse(v[j].x - r[j], m[st].x, s[st].x);
            online_lse(v[j].y - r[j], m[st].y, s[st].y);
            online_lse(v[j].z - r[j], m[st].z, s[st].z);
            online_lse(v[j].w - r[j], m[st].w, s[st].w);
        }
    }
    float4 M = m[0], S = s[0];
    #pragma unroll
    for (int j=1;j<4;j++){
        merge_lse(M.x, S.x, m[j].x, s[j].x);
        merge_lse(M.y, S.y, m[j].y, s[j].y);
        merge_lse(M.z, S.z, m[j].z, s[j].z);
        merge_lse(M.w, S.w, m[j].w, s[j].w);
    }
    __shared__ float4 sm16[16][16], ss16[16][16];
    sm16[rg][cg] = M; ss16[rg][cg] = S;
    __syncthreads();
    if (rg == 0){
        #pragma unroll
        for (int g=1; g<16; g++){
            float4 mg = sm16[g][cg], sg = ss16[g][cg];
            merge_lse(M.x, S.x, mg.x, sg.x);
            merge_lse(M.y, S.y, mg.y, sg.y);
            merge_lse(M.z, S.z, mg.z, sg.z);
            merge_lse(M.w, S.w, mg.w, sg.w);
        }
        int j = b*NNODE + chunk*64 + cg*4;
        d_Cv[j+0] = M.x + __logf(S.x);
        d_Cv[j+1] = M.y + __logf(S.y);
        d_Cv[j+2] = M.z + __logf(S.z);
        d_Cv[j+3] = M.w + __logf(S.w);
    }
}

__global__ void k_col_T(const float* __restrict__ Z){
    int b     = blockIdx.x >> 4;
    int chunk = blockIdx.x & 15;
    int cg    = threadIdx.x & 15;
    int rg    = threadIdx.x >> 4;
    __shared__ float rs[NNODE];
    for (int k=threadIdx.x; k<NNODE; k+=256) rs[k] = d_Rv[b*NNODE + k];
    __syncthreads();
    float4 cj = *((const float4*)(d_Cv + b*NNODE) + chunk*16 + cg);
    const float4* z = (const float4*)(Z + (size_t)b*NNODE*NNODE) + chunk*16 + cg;
    float4 s = {0.f,0.f,0.f,0.f};
    int i0 = rg*64;
    for (int i=i0; i<i0+64; i+=8){
        float4 v[8]; float r[8];
        #pragma unroll
        for (int j=0;j<8;j++){ v[j] = z[(size_t)(i+j)*256]; r[j] = rs[i+j]; }
        #pragma unroll
        for (int j=0;j<8;j++){
            s.x += __expf(v[j].x - r[j] - cj.x);
            s.y += __expf(v[j].y - r[j] - cj.y);
            s.z += __expf(v[j].z - r[j] - cj.z);
            s.w += __expf(v[j].w - r[j] - cj.w);
        }
    }
    __shared__ float4 ss16[16][16];
    ss16[rg][cg] = s;
    __syncthreads();
    if (rg == 0){
        #pragma unroll
        for (int g=1; g<16; g++){
            float4 sg = ss16[g][cg];
            s.x += sg.x; s.y += sg.y; s.z += sg.z; s.w += sg.w;
        }
        int j = b*NNODE + chunk*64 + cg*4;
        d_Tv[j+0]=s.x; d_Tv[j+1]=s.y; d_Tv[j+2]=s.z; d_Tv[j+3]=s.w;
    }
}

__global__ void k_final(const float* __restrict__ Z, float* __restrict__ P){
    size_t t = (size_t)blockIdx.x*256 + threadIdx.x;
    int row = (int)(t >> 10);
    int b   = row >> 10;
    int j   = (int)(t & 1023);
    P[t] = __expf(Z[t] - d_Rv[row] - d_Cv[b*NNODE + j]) / d_Tv[b*NNODE + j];
}

extern "C" void kernel_launch(void* const* d_in, const int* in_sizes, int n_in,
                              void* d_out, int out_size) {
    const float* X      = (const float*)d_in[0];
    const float* adj    = (const float*)d_in[1];
    const float* w_in   = (const float*)d_in[2];
    const float* b_in   = (const float*)d_in[3];
    const float* cw1    = (const float*)d_in[4];
    const float* cb1    = (const float*)d_in[5];
    const float* cw2    = (const float*)d_in[6];
    const float* cb2    = (const float*)d_in[7];
    const float* ca     = (const float*)d_in[8];
    const float* m1w    = (const float*)d_in[9];
    const float* m1b    = (const float*)d_in[10];
    const float* m2w    = (const float*)d_in[11];
    const float* m2b    = (const float*)d_in[12];
    float* Pout = (float*)d_out;
    float* Z0   = Pout + (size_t)TOTEL;

    float *hid, *hs, *g, *u1, *u2, *u3, *u4, *hp, *mid, *lg;
    cudaGetSymbolAddress((void**)&hid, d_hid);
    cudaGetSymbolAddress((void**)&hs,  d_hs);
    cudaGetSymbolAddress((void**)&g,   d_g);
    cudaGetSymbolAddress((void**)&u1,  d_u1);
    cudaGetSymbolAddress((void**)&u2,  d_u2);
    cudaGetSymbolAddress((void**)&u3,  d_u3);
    cudaGetSymbolAddress((void**)&u4,  d_u4);
    cudaGetSymbolAddress((void**)&hp,  d_hp);
    cudaGetSymbolAddress((void**)&mid, d_mid);
    cudaGetSymbolAddress((void**)&lg,  d_logits);
    float *dis, *invdeg;
    cudaGetSymbolAddress((void**)&dis,    d_dis);
    cudaGetSymbolAddress((void**)&invdeg, d_invdeg);

    k_adj_stats<<<NROWS/8, 256>>>(adj);

    // h0 = X @ w_in^T + b_in
    k_gemm_nt<<<dim3(2,128), 256>>>(X, 128, w_in, 128, b_in, hid, 768, 0);

    dim3 tg(2, 8, 16);
    for (int l = 0; l < 2; l++){
        int off  = 256*l;
        int offn = 256*(l+1);
        k_scale_hs<<<NROWS*HD/256, 256>>>(off);
        k_mma<<<tg, 256>>>(adj, hs, 256, g, 1, hs, 256, dis);
        k_mma<<<tg, 256>>>(adj, hid+off, 768, u1, 2, hid+off, 768, invdeg);
        k_mma<<<tg, 256>>>(adj, u1, 256, u2, 2, u1, 256, invdeg);
        k_mma<<<tg, 256>>>(adj, u2, 256, u3, 2, u2, 256, invdeg);
        k_mma<<<tg, 256>>>(adj, u3, 256, u4, 2, u3, 256, invdeg);
        k_attn<<<NROWS, 256>>>(off, ca + l*512);
        k_gemm_nt<<<dim3(2,128), 256>>>(hp,  256, cw1 + l*65536, 256, cb1 + l*256, mid, 256, 1);
        k_gemm_nt<<<dim3(2,128), 256>>>(mid, 256, cw2 + l*65536, 256, cb2 + l*256, hid + offn, 768, 1);
    }

    // mlp1 + mlp2
    k_gemm_nt<<<dim3(2,128), 256>>>(hid, 768, m1w, 768, m1b, mid, 256, 1);
    k_gemm_nt<<<dim3(8,128), 256>>>(mid, 256, m2w, 256, m2b, lg, 1024, 2);

    // Z0 = (logits + gumbel)/tau  (gsinit output)
    k_z0<<<TOTEL/256, 256>>>(Z0);

    // Sinkhorn: rank-1 log-domain state (R, C)
    k_zeroC<<<NROWS/256, 256>>>();
    for (int it = 0; it < 20; it++){
        k_row_lse<<<NROWS/8, 256>>>(Z0);
        k_col_lse<<<256, 256>>>(Z0);
    }
    k_row_lse<<<NROWS/8, 256>>>(Z0);
    k_col_T  <<<256, 256>>>(Z0);
    k_final  <<<TOTEL/256, 256>>>(Z0, Pout);
}